// round 1
// baseline (speedup 1.0000x reference)
#include <cuda_runtime.h>
#include <stdint.h>

// Gaussian splatting preprocess: fully fused, one thread per point.
// Memory-bound: 56 B in + 88 B out per point.

__device__ __forceinline__ float scalar_to_float(const int* p) {
    // Scalars should be int32 (1000, 1920, 1080, 16). If the harness stored
    // them as float32, the raw bits would be a large int (e.g. 1000.0f ->
    // 0x447A0000). Decode defensively.
    int v = __ldg(p);
    if (v >= 0 && v < (1 << 23)) return (float)v;
    return __int_as_float(v);
}

__global__ __launch_bounds__(256)
void gs_pre_kernel(const float* __restrict__ points,
                   const float* __restrict__ quats,
                   const float* __restrict__ scales,
                   const float* __restrict__ colors,
                   const float* __restrict__ opacity,
                   const float* __restrict__ E,    // 16 floats, row-major 4x4
                   const float* __restrict__ I,    // 16 floats, row-major 4x4
                   const int* __restrict__ p_fx,
                   const int* __restrict__ p_fy,
                   const int* __restrict__ p_w,
                   const int* __restrict__ p_h,
                   const int* __restrict__ p_tile,
                   float* __restrict__ out,
                   int n)
{
    int i = blockIdx.x * blockDim.x + threadIdx.x;
    if (i >= n) return;

    const float fx   = scalar_to_float(p_fx);
    const float fy   = scalar_to_float(p_fy);
    const float fw   = scalar_to_float(p_w);
    const float fh   = scalar_to_float(p_h);
    const float tile = scalar_to_float(p_tile);

    // tan(2*atan(w/(2f))/2) == w/(2f) exactly.
    const float clipX = 1.3f * (fw / (2.0f * fx));
    const float clipY = 1.3f * (fh / (2.0f * fy));

    float e[16], ii[16];
#pragma unroll
    for (int k = 0; k < 16; k++) { e[k] = __ldg(E + k); ii[k] = __ldg(I + k); }

    // ---- loads ----
    const float p0 = __ldg(points + 3*i + 0);
    const float p1 = __ldg(points + 3*i + 1);
    const float p2 = __ldg(points + 3*i + 2);

    const float4 q = *reinterpret_cast<const float4*>(quats + 4*i);
    const float s0 = __ldg(scales + 3*i + 0);
    const float s1 = __ldg(scales + 3*i + 1);
    const float s2 = __ldg(scales + 3*i + 2);

    // ---- quaternion -> rotation ----
    const float qn = rsqrtf(q.x*q.x + q.y*q.y + q.z*q.z + q.w*q.w);
    const float r  = q.x * qn;
    const float qx = q.y * qn;
    const float qy = q.z * qn;
    const float qz = q.w * qn;

    const float R00 = 1.0f - 2.0f*(qy*qy + qz*qz);
    const float R01 = 2.0f*(qx*qy - r*qz);
    const float R02 = 2.0f*(qx*qz + r*qy);
    const float R10 = 2.0f*(qx*qy + r*qz);
    const float R11 = 1.0f - 2.0f*(qx*qx + qz*qz);
    const float R12 = 2.0f*(qy*qz - r*qx);
    const float R20 = 2.0f*(qx*qz - r*qy);
    const float R21 = 2.0f*(qy*qz + r*qx);
    const float R22 = 1.0f - 2.0f*(qx*qx + qy*qy);

    // M = R * diag-broadcast(scales along columns)
    const float M00 = R00*s0, M01 = R01*s1, M02 = R02*s2;
    const float M10 = R10*s0, M11 = R11*s1, M12 = R12*s2;
    const float M20 = R20*s0, M21 = R21*s1, M22 = R22*s2;

    // cov3d = M M^T (symmetric)
    const float S00 = M00*M00 + M01*M01 + M02*M02;
    const float S01 = M00*M10 + M01*M11 + M02*M12;
    const float S02 = M00*M20 + M01*M21 + M02*M22;
    const float S11 = M10*M10 + M11*M11 + M12*M12;
    const float S12 = M10*M20 + M11*M21 + M12*M22;
    const float S22 = M20*M20 + M21*M21 + M22*M22;

    // pc = [p,1] @ E  (row-vector convention, E[i][j] = e[4i+j])
    const float pc0 = p0*e[0] + p1*e[4] + p2*e[8]  + e[12];
    const float pc1 = p0*e[1] + p1*e[5] + p2*e[9]  + e[13];
    const float pc2 = p0*e[2] + p1*e[6] + p2*e[10] + e[14];
    const float pc3 = p0*e[3] + p1*e[7] + p2*e[11] + e[15];

    const float zc    = pc2;
    const bool  zmask = (zc > 0.2f);
    const float zs    = zmask ? zc : 1.0f;

    const float xv = fminf(fmaxf(pc0 / zs, -clipX), clipX) * zc;
    const float yv = fminf(fmaxf(pc1 / zs, -clipY), clipY) * zc;

    const float j00 = fx / zs;
    const float j11 = fy / zs;
    const float zs2 = zs * zs;
    const float j02 = -(fx * xv) / zs2;
    const float j12 = -(fy * yv) / zs2;

    // T columns 0 and 1 (J row 2 is zero): T[i][k] = sum_j W[i][j]*J[k][j]
    const float t00 = e[0]*j00 + e[2]*j02;
    const float t01 = e[4]*j00 + e[6]*j02;
    const float t02 = e[8]*j00 + e[10]*j02;
    const float t10 = e[1]*j11 + e[2]*j12;
    const float t11 = e[5]*j11 + e[6]*j12;
    const float t12 = e[9]*j11 + e[10]*j12;

    // C = T^T S T (only 2x2 block needed). u = S*t0, v = S*t1.
    const float u0 = S00*t00 + S01*t01 + S02*t02;
    const float u1 = S01*t00 + S11*t01 + S12*t02;
    const float u2 = S02*t00 + S12*t01 + S22*t02;
    const float v0 = S00*t10 + S01*t11 + S02*t12;
    const float v1 = S01*t10 + S11*t11 + S12*t12;
    const float v2 = S02*t10 + S12*t11 + S22*t12;

    const float C00 = t00*u0 + t01*u1 + t02*u2;
    const float C01 = t10*u0 + t11*u1 + t12*u2;   // == C10 exactly (S symmetric)
    const float C11 = t10*v0 + t11*v1 + t12*v2;

    const float a = C00 + 0.3f;
    const float d = C11 + 0.3f;
    const float b = C01;

    // ndc = pc @ I
    const float n0 = pc0*ii[0] + pc1*ii[4] + pc2*ii[8]  + pc3*ii[12];
    const float n1 = pc0*ii[1] + pc1*ii[5] + pc2*ii[9]  + pc3*ii[13];
    const float n2 = pc0*ii[2] + pc1*ii[6] + pc2*ii[10] + pc3*ii[14];
    const float n3 = pc0*ii[3] + pc1*ii[7] + pc2*ii[11] + pc3*ii[15];

    const float wsafe = zmask ? n3 : 1.0f;
    const float nx = n0 / wsafe;
    const float ny = n1 / wsafe;
    const float nz = n2;

    const bool mask = (nz > 0.2f) && (nx < 1.3f) && (nx > -1.3f)
                                  && (ny < 1.3f) && (ny > -1.3f);

    const float det  = a*d - b*b;
    const float dets = (fabsf(det) < 1e-12f) ? 1e-12f : det;
    const float idet = 1.0f / dets;

    const float mid  = 0.5f * (a + d);
    const float sv   = sqrtf(fmaxf(mid*mid - det, 0.1f));
    const float lmax = mid + sv;                 // max(mid+s, mid-s), s >= 0
    const float radius = ceilf(3.0f * sqrtf(fmaxf(lmax, 1e-6f)));

    const float px = ((nx + 1.0f) * fw - 1.0f) * 0.5f;
    const float py = ((ny + 1.0f) * fh - 1.0f) * 0.5f;

    const int max_tx = (int)ceilf(fw / tile) - 1;
    const int max_ty = (int)ceilf(fh / tile) - 1;

    // astype(int32) truncates toward zero == C cast; clip AFTER cast.
    int tlx = (int)((px - radius) / tile);
    int tly = (int)((py - radius) / tile);
    int brx = (int)((px + radius) / tile);
    int bry = (int)((py + radius) / tile);
    tlx = min(max(tlx, 0), max_tx);
    tly = min(max(tly, 0), max_ty);
    brx = min(max(brx, 0), max_tx);
    bry = min(max(bry, 0), max_ty);

    const int span  = max(brx + 1 - tlx, 1) * max(bry + 1 - tly, 1);
    const int tiles = mask ? span : 0;

    const float c0 = __ldg(colors + 3*i + 0);
    const float c1 = __ldg(colors + 3*i + 1);
    const float c2 = __ldg(colors + 3*i + 2);
    const float op = __ldg(opacity + i);

    // float_out row (16 floats), zeroed when masked out
    float4 f0, f1, f2, f3;
    if (mask) {
        f0 = make_float4(px, py, nz, a);
        f1 = make_float4(b, b, d, d * idet);
        f2 = make_float4(-b * idet, -b * idet, a * idet, radius);
        f3 = make_float4(c0, c1, c2, op);
    } else {
        f0 = make_float4(0.f, 0.f, 0.f, 0.f);
        f1 = f0; f2 = f0; f3 = f0;
    }

    float4* o4 = reinterpret_cast<float4*>(out) + (size_t)i * 4;
    o4[0] = f0; o4[1] = f1; o4[2] = f2; o4[3] = f3;

    const size_t N = (size_t)n;
    out[16*N + i] = (float)tiles;
    out[17*N + i] = (float)tlx;
    out[18*N + i] = (float)tly;
    out[19*N + i] = (float)brx;
    out[20*N + i] = (float)bry;
    out[21*N + i] = mask ? 1.0f : 0.0f;
}

extern "C" void kernel_launch(void* const* d_in, const int* in_sizes, int n_in,
                              void* d_out, int out_size)
{
    const float* points  = (const float*)d_in[0];
    const float* quats   = (const float*)d_in[1];
    const float* scales  = (const float*)d_in[2];
    const float* colors  = (const float*)d_in[3];
    const float* opacity = (const float*)d_in[4];
    const float* E       = (const float*)d_in[5];
    const float* I       = (const float*)d_in[6];
    const int*   p_fx    = (const int*)d_in[7];
    const int*   p_fy    = (const int*)d_in[8];
    const int*   p_w     = (const int*)d_in[9];
    const int*   p_h     = (const int*)d_in[10];
    const int*   p_tile  = (const int*)d_in[11];

    const int n = in_sizes[0] / 3;
    float* out = (float*)d_out;

    const int threads = 256;
    const int blocks  = (n + threads - 1) / threads;
    gs_pre_kernel<<<blocks, threads>>>(points, quats, scales, colors, opacity,
                                       E, I, p_fx, p_fy, p_w, p_h, p_tile,
                                       out, n);
}

// round 2
// speedup vs baseline: 1.3534x; 1.3534x over previous
#include <cuda_runtime.h>
#include <stdint.h>

// Gaussian splatting preprocess: fully fused, one thread per point.
// R2: register-capped for 5 blocks/SM, divisions consolidated to 2,
//     all per-point loads front-batched for MLP.

__device__ __forceinline__ float scalar_to_float(const int* p) {
    int v = __ldg(p);
    if (v >= 0 && v < (1 << 23)) return (float)v;
    return __int_as_float(v);
}

__global__ __launch_bounds__(256, 5)
void gs_pre_kernel(const float* __restrict__ points,
                   const float* __restrict__ quats,
                   const float* __restrict__ scales,
                   const float* __restrict__ colors,
                   const float* __restrict__ opacity,
                   const float* __restrict__ E,    // 16 floats, row-major 4x4
                   const float* __restrict__ I,    // 16 floats, row-major 4x4
                   const int* __restrict__ p_fx,
                   const int* __restrict__ p_fy,
                   const int* __restrict__ p_w,
                   const int* __restrict__ p_h,
                   const int* __restrict__ p_tile,
                   float* __restrict__ out,
                   int n)
{
    int i = blockIdx.x * blockDim.x + threadIdx.x;
    if (i >= n) return;

    // ---- front-batched per-point loads (maximize outstanding LDGs) ----
    const float p0 = __ldg(points + 3*i + 0);
    const float p1 = __ldg(points + 3*i + 1);
    const float p2 = __ldg(points + 3*i + 2);
    const float4 q = *reinterpret_cast<const float4*>(quats + 4*i);
    const float s0 = __ldg(scales + 3*i + 0);
    const float s1 = __ldg(scales + 3*i + 1);
    const float s2 = __ldg(scales + 3*i + 2);
    const float c0 = __ldg(colors + 3*i + 0);
    const float c1 = __ldg(colors + 3*i + 1);
    const float c2 = __ldg(colors + 3*i + 2);
    const float op = __ldg(opacity + i);

    const float fx   = scalar_to_float(p_fx);
    const float fy   = scalar_to_float(p_fy);
    const float fw   = scalar_to_float(p_w);
    const float fh   = scalar_to_float(p_h);
    const float tile = scalar_to_float(p_tile);
    const float rtile = 1.0f / tile;   // tile is a power of 2 -> exact

    // tan(2*atan(w/(2f))/2) == w/(2f) exactly.
    const float clipX = 1.3f * (fw / (2.0f * fx));
    const float clipY = 1.3f * (fh / (2.0f * fy));

    // ---- quaternion -> rotation ----
    const float qn = rsqrtf(q.x*q.x + q.y*q.y + q.z*q.z + q.w*q.w);
    const float r  = q.x * qn;
    const float qx = q.y * qn;
    const float qy = q.z * qn;
    const float qz = q.w * qn;

    // M = R * scales (columns)
    const float M00 = (1.0f - 2.0f*(qy*qy + qz*qz)) * s0;
    const float M01 = (2.0f*(qx*qy - r*qz))         * s1;
    const float M02 = (2.0f*(qx*qz + r*qy))         * s2;
    const float M10 = (2.0f*(qx*qy + r*qz))         * s0;
    const float M11 = (1.0f - 2.0f*(qx*qx + qz*qz)) * s1;
    const float M12 = (2.0f*(qy*qz - r*qx))         * s2;
    const float M20 = (2.0f*(qx*qz - r*qy))         * s0;
    const float M21 = (2.0f*(qy*qz + r*qx))         * s1;
    const float M22 = (1.0f - 2.0f*(qx*qx + qy*qy)) * s2;

    // cov3d = M M^T (symmetric)
    const float S00 = M00*M00 + M01*M01 + M02*M02;
    const float S01 = M00*M10 + M01*M11 + M02*M12;
    const float S02 = M00*M20 + M01*M21 + M02*M22;
    const float S11 = M10*M10 + M11*M11 + M12*M12;
    const float S12 = M10*M20 + M11*M21 + M12*M22;
    const float S22 = M20*M20 + M21*M21 + M22*M22;

    // pc = [p,1] @ E
    const float pc0 = p0*__ldg(E+0) + p1*__ldg(E+4) + p2*__ldg(E+8)  + __ldg(E+12);
    const float pc1 = p0*__ldg(E+1) + p1*__ldg(E+5) + p2*__ldg(E+9)  + __ldg(E+13);
    const float pc2 = p0*__ldg(E+2) + p1*__ldg(E+6) + p2*__ldg(E+10) + __ldg(E+14);
    const float pc3 = p0*__ldg(E+3) + p1*__ldg(E+7) + p2*__ldg(E+11) + __ldg(E+15);

    const float zc    = pc2;
    const bool  zmask = (zc > 0.2f);
    const float zs    = zmask ? zc : 1.0f;
    const float rz    = 1.0f / zs;          // single divide for camera path

    const float xv = fminf(fmaxf(pc0 * rz, -clipX), clipX) * zc;
    const float yv = fminf(fmaxf(pc1 * rz, -clipY), clipY) * zc;

    const float j00 = fx * rz;
    const float j11 = fy * rz;
    const float rz2 = rz * rz;
    const float j02 = -(fx * xv) * rz2;
    const float j12 = -(fy * yv) * rz2;

    // T columns 0 and 1 (J row 2 is zero)
    const float t00 = __ldg(E+0)*j00 + __ldg(E+2)*j02;
    const float t01 = __ldg(E+4)*j00 + __ldg(E+6)*j02;
    const float t02 = __ldg(E+8)*j00 + __ldg(E+10)*j02;
    const float t10 = __ldg(E+1)*j11 + __ldg(E+2)*j12;
    const float t11 = __ldg(E+5)*j11 + __ldg(E+6)*j12;
    const float t12 = __ldg(E+9)*j11 + __ldg(E+10)*j12;

    // C = T^T S T, 2x2 block
    const float u0 = S00*t00 + S01*t01 + S02*t02;
    const float u1 = S01*t00 + S11*t01 + S12*t02;
    const float u2 = S02*t00 + S12*t01 + S22*t02;
    const float v0 = S00*t10 + S01*t11 + S02*t12;
    const float v1 = S01*t10 + S11*t11 + S12*t12;
    const float v2 = S02*t10 + S12*t11 + S22*t12;

    const float a = t00*u0 + t01*u1 + t02*u2 + 0.3f;
    const float b = t10*u0 + t11*u1 + t12*u2;     // == C10 exactly
    const float d = t10*v0 + t11*v1 + t12*v2 + 0.3f;

    // ndc = pc @ I
    const float n0 = pc0*__ldg(I+0) + pc1*__ldg(I+4) + pc2*__ldg(I+8)  + pc3*__ldg(I+12);
    const float n1 = pc0*__ldg(I+1) + pc1*__ldg(I+5) + pc2*__ldg(I+9)  + pc3*__ldg(I+13);
    const float n2 = pc0*__ldg(I+2) + pc1*__ldg(I+6) + pc2*__ldg(I+10) + pc3*__ldg(I+14);
    const float n3 = pc0*__ldg(I+3) + pc1*__ldg(I+7) + pc2*__ldg(I+11) + pc3*__ldg(I+15);

    const float rw = 1.0f / (zmask ? n3 : 1.0f);   // second divide
    const float nx = n0 * rw;
    const float ny = n1 * rw;
    const float nz = n2;

    const bool mask = (nz > 0.2f) && (nx < 1.3f) && (nx > -1.3f)
                                  && (ny < 1.3f) && (ny > -1.3f);

    const float det  = a*d - b*b;
    const float dets = (fabsf(det) < 1e-12f) ? 1e-12f : det;
    const float idet = 1.0f / dets;               // third divide (masked rows only matter)

    const float mid  = 0.5f * (a + d);
    const float sv   = sqrtf(fmaxf(mid*mid - det, 0.1f));
    const float radius = ceilf(3.0f * sqrtf(fmaxf(mid + sv, 1e-6f)));

    const float px = ((nx + 1.0f) * fw - 1.0f) * 0.5f;
    const float py = ((ny + 1.0f) * fh - 1.0f) * 0.5f;

    const int max_tx = (int)ceilf(fw * rtile) - 1;
    const int max_ty = (int)ceilf(fh * rtile) - 1;

    int tlx = (int)((px - radius) * rtile);
    int tly = (int)((py - radius) * rtile);
    int brx = (int)((px + radius) * rtile);
    int bry = (int)((py + radius) * rtile);
    tlx = min(max(tlx, 0), max_tx);
    tly = min(max(tly, 0), max_ty);
    brx = min(max(brx, 0), max_tx);
    bry = min(max(bry, 0), max_ty);

    const int span  = max(brx + 1 - tlx, 1) * max(bry + 1 - tly, 1);
    const int tiles = mask ? span : 0;

    float4 f0, f1, f2, f3;
    if (mask) {
        f0 = make_float4(px, py, nz, a);
        f1 = make_float4(b, b, d, d * idet);
        f2 = make_float4(-b * idet, -b * idet, a * idet, radius);
        f3 = make_float4(c0, c1, c2, op);
    } else {
        f0 = make_float4(0.f, 0.f, 0.f, 0.f);
        f1 = f0; f2 = f0; f3 = f0;
    }

    float4* o4 = reinterpret_cast<float4*>(out) + (size_t)i * 4;
    o4[0] = f0; o4[1] = f1; o4[2] = f2; o4[3] = f3;

    const size_t N = (size_t)n;
    out[16*N + i] = (float)tiles;
    out[17*N + i] = (float)tlx;
    out[18*N + i] = (float)tly;
    out[19*N + i] = (float)brx;
    out[20*N + i] = (float)bry;
    out[21*N + i] = mask ? 1.0f : 0.0f;
}

extern "C" void kernel_launch(void* const* d_in, const int* in_sizes, int n_in,
                              void* d_out, int out_size)
{
    const float* points  = (const float*)d_in[0];
    const float* quats   = (const float*)d_in[1];
    const float* scales  = (const float*)d_in[2];
    const float* colors  = (const float*)d_in[3];
    const float* opacity = (const float*)d_in[4];
    const float* E       = (const float*)d_in[5];
    const float* I       = (const float*)d_in[6];
    const int*   p_fx    = (const int*)d_in[7];
    const int*   p_fy    = (const int*)d_in[8];
    const int*   p_w     = (const int*)d_in[9];
    const int*   p_h     = (const int*)d_in[10];
    const int*   p_tile  = (const int*)d_in[11];

    const int n = in_sizes[0] / 3;
    float* out = (float*)d_out;

    const int threads = 256;
    const int blocks  = (n + threads - 1) / threads;
    gs_pre_kernel<<<blocks, threads>>>(points, quats, scales, colors, opacity,
                                       E, I, p_fx, p_fy, p_w, p_h, p_tile,
                                       out, n);
}